// round 14
// baseline (speedup 1.0000x reference)
#include <cuda_runtime.h>
#include <cstdint>

#define D 64
// k1: 3 blocks/SM -> 444 blocks, X:Y = 3:5
#define K1GX 166
#define K1GY 278
// k3: 3 blocks/SM -> 444 blocks, X:Y = 3:5
#define K3GX 167
#define K3GY 277

// Global accumulators / tables (no allocation allowed)
__device__ float g_P[768];                 // [0:384) Px_stored, [384:768) Py_stored
__device__ float g_cx[384], g_dx[384];
__device__ float g_cy[384], g_dy[384];

struct K1Args {
    const float* embX; const int* idsX; int nX;
    const float* embY; const int* idsY; int nY;
    const float* wX[6];   // uu(buy,cart,pv), iu(buy,cart,pv)
    const float* wY[6];   // ui(buy,cart,pv), ii(buy,cart,pv)
};
struct K2Args {
    const float* w[12];    // logical: buy_uu, buy_ui, buy_iu, buy_ii, cart_*, pv_*
    const float* w1[12];
    const float* edges[3];
};
struct K3Args {
    const float* embX; const int* idsX; int nX; float* outX;
    const float* embY; const int* idsY; int nY; float* outY;
};

// packed fp32 FMA (Blackwell f32x2 pipe)
__device__ __forceinline__ float2 ffma2(float2 a, float2 b, float2 c) {
    float2 d;
    asm("{\n\t"
        ".reg .b64 Ar,Br,Cr,Dr;\n\t"
        "mov.b64 Ar,{%2,%3};\n\t"
        "mov.b64 Br,{%4,%5};\n\t"
        "mov.b64 Cr,{%6,%7};\n\t"
        "fma.rn.f32x2 Dr,Ar,Br,Cr;\n\t"
        "mov.b64 {%0,%1},Dr;\n\t"
        "}" : "=f"(d.x), "=f"(d.y)
            : "f"(a.x), "f"(a.y), "f"(b.x), "f"(b.y), "f"(c.x), "f"(c.y));
    return d;
}
__device__ __forceinline__ float2 fmul2(float2 a, float2 b) {
    return ffma2(a, b, make_float2(0.f, 0.f));
}
__device__ __forceinline__ float dot8(float4 a0, float4 a1, float4 b0, float4 b1) {
    float2 s = fmul2(make_float2(a0.x, a0.y), make_float2(b0.x, b0.y));
    s = ffma2(make_float2(a0.z, a0.w), make_float2(b0.z, b0.w), s);
    s = ffma2(make_float2(a1.x, a1.y), make_float2(b1.x, b1.y), s);
    s = ffma2(make_float2(a1.z, a1.w), make_float2(b1.z, b1.w), s);
    return s.x + s.y;
}

// ---------------------------------------------------------------------------
__global__ void k0_zero() { g_P[threadIdx.x] = 0.0f; }

// ---------------------------------------------------------------------------
// k1: p_t(stored) = sum_rows (x . 0.1*w_t) x_raw.  (R13 version: proven)
// 8 lanes/row dense lines; warp pair shares 4 rows, t-split; w in shared.
// Software-pipelined: next iteration's ids + emb loads issue before compute.
// ---------------------------------------------------------------------------
__global__ __launch_bounds__(256, 3) void k1_gramvec(K1Args A)
{
    const int side = (blockIdx.x >= K1GX) ? 1 : 0;
    const int bid  = side ? (blockIdx.x - K1GX) : blockIdx.x;
    const int nb   = side ? K1GY : K1GX;
    const float* __restrict__ emb = side ? A.embY : A.embX;
    const int*   __restrict__ ids = side ? A.idsY : A.idsX;
    const int n = side ? A.nY : A.nX;

    __shared__ float sw[384];     // 0.1 * w
    __shared__ float sp[384];
    const int tid  = threadIdx.x;
    const int wid  = tid >> 5;
    const int lane = tid & 31;
    const int tg   = (wid & 1) * 3;
    const int rsl  = ((wid >> 1) << 2) + (lane >> 3);
    const int g    = lane & 7;
    const int colA = g << 2;
    const int colB = 32 + (g << 2);

    {
        const float* const* Wp = side ? A.wY : A.wX;
        for (int i = tid; i < 384; i += 256) {
            sw[i] = 0.1f * Wp[i >> 6][i & 63];
            sp[i] = 0.0f;
        }
    }
    __syncthreads();

    float2 accA[3][2], accB[3][2];
#pragma unroll
    for (int t = 0; t < 3; t++) {
        accA[t][0] = accA[t][1] = make_float2(0.f, 0.f);
        accB[t][0] = accB[t][1] = make_float2(0.f, 0.f);
    }

    int base = bid * 16;
    const float* p0 = emb + ((size_t)ids[base + rsl] << 6);
    float4 xA = *reinterpret_cast<const float4*>(p0 + colA);
    float4 xB = *reinterpret_cast<const float4*>(p0 + colB);

    for (;;) {
        const int nbase = base + nb * 16;
        const bool more = nbase < n;
        float4 xAn, xBn;
        if (more) {
            const float* pn = emb + ((size_t)ids[nbase + rsl] << 6);
            xAn = *reinterpret_cast<const float4*>(pn + colA);
            xBn = *reinterpret_cast<const float4*>(pn + colB);
        }

        float a[3];
#pragma unroll
        for (int t = 0; t < 3; t++) {
            const float4 wA = *reinterpret_cast<const float4*>(sw + ((tg + t) << 6) + colA);
            const float4 wB = *reinterpret_cast<const float4*>(sw + ((tg + t) << 6) + colB);
            a[t] = dot8(xA, xB, wA, wB);
        }
#pragma unroll
        for (int off = 4; off; off >>= 1)
#pragma unroll
            for (int t = 0; t < 3; t++)
                a[t] += __shfl_xor_sync(0xffffffffu, a[t], off);
#pragma unroll
        for (int t = 0; t < 3; t++) {
            const float2 av = make_float2(a[t], a[t]);
            accA[t][0] = ffma2(av, make_float2(xA.x, xA.y), accA[t][0]);
            accA[t][1] = ffma2(av, make_float2(xA.z, xA.w), accA[t][1]);
            accB[t][0] = ffma2(av, make_float2(xB.x, xB.y), accB[t][0]);
            accB[t][1] = ffma2(av, make_float2(xB.z, xB.w), accB[t][1]);
        }

        if (!more) break;
        base = nbase;
        xA = xAn; xB = xBn;
    }

#pragma unroll
    for (int off = 8; off <= 16; off <<= 1)
#pragma unroll
        for (int t = 0; t < 3; t++)
#pragma unroll
            for (int j = 0; j < 2; j++) {
                accA[t][j].x += __shfl_xor_sync(0xffffffffu, accA[t][j].x, off);
                accA[t][j].y += __shfl_xor_sync(0xffffffffu, accA[t][j].y, off);
                accB[t][j].x += __shfl_xor_sync(0xffffffffu, accB[t][j].x, off);
                accB[t][j].y += __shfl_xor_sync(0xffffffffu, accB[t][j].y, off);
            }

    if (lane < 8) {
#pragma unroll
        for (int t = 0; t < 3; t++) {
            atomicAdd(&sp[((tg + t) << 6) + colA],     accA[t][0].x);
            atomicAdd(&sp[((tg + t) << 6) + colA + 1], accA[t][0].y);
            atomicAdd(&sp[((tg + t) << 6) + colA + 2], accA[t][1].x);
            atomicAdd(&sp[((tg + t) << 6) + colA + 3], accA[t][1].y);
            atomicAdd(&sp[((tg + t) << 6) + colB],     accB[t][0].x);
            atomicAdd(&sp[((tg + t) << 6) + colB + 1], accB[t][0].y);
            atomicAdd(&sp[((tg + t) << 6) + colB + 2], accB[t][1].x);
            atomicAdd(&sp[((tg + t) << 6) + colB + 3], accB[t][1].y);
        }
    }
    __syncthreads();

    float* gp = g_P + side * 384;
    for (int i = tid; i < 384; i += 256)
        atomicAdd(&gp[i], sp[i]);
}

// ---------------------------------------------------------------------------
// k2: build c/d tables. Blocks 0..11: one (side,term). Block 12: edge copy.
// p_true = 0.1 * p_stored -> coef = 0.25 * 0.1 * W_b
// ---------------------------------------------------------------------------
__global__ __launch_bounds__(64) void k2_build(K2Args a, float* __restrict__ edge_out)
{
    const int blk = blockIdx.x;
    const int j   = threadIdx.x;

    if (blk == 12) {
#pragma unroll
        for (int e = 0; e < 3; e++)
            edge_out[e * 64 + j] = a.edges[e][j];
        return;
    }

    const int side = blk / 6;
    const int t    = blk % 6;
    const int b    = t % 3;

    const float* p; const float* W1; const float* c;
    if (side == 0) {
        if (t < 3) { p = &g_P[b * 64];           W1 = a.w1[4 * b + 0]; c = a.w[4 * b + 0]; } // uu
        else       { p = &g_P[384 + b * 64];     W1 = a.w1[4 * b + 1]; c = a.w[4 * b + 1]; } // ui
    } else {
        if (t < 3) { p = &g_P[384 + (3 + b) * 64]; W1 = a.w1[4 * b + 3]; c = a.w[4 * b + 3]; } // ii
        else       { p = &g_P[(3 + b) * 64];       W1 = a.w1[4 * b + 2]; c = a.w[4 * b + 2]; } // iu
    }
    const float coef = 0.025f * ((b == 0) ? 0.6f : (b == 1) ? 0.3f : 0.1f);

    float u0 = 0.f, u1 = 0.f, u2 = 0.f, u3 = 0.f;
#pragma unroll
    for (int k = 0; k < 64; k += 4) {
        u0 += p[k + 0] * W1[(k + 0) * 64 + j];
        u1 += p[k + 1] * W1[(k + 1) * 64 + j];
        u2 += p[k + 2] * W1[(k + 2) * 64 + j];
        u3 += p[k + 3] * W1[(k + 3) * 64 + j];
    }
    const float d = coef * ((u0 + u1) + (u2 + u3));
    if (side == 0) { g_dx[t * 64 + j] = d; g_cx[t * 64 + j] = c[j]; }
    else           { g_dy[t * 64 + j] = d; g_cy[t * 64 + j] = c[j]; }
}

// ---------------------------------------------------------------------------
// k3: out = 0.05*x_raw + sum_t (x_raw . 0.1c_t) d_t
// 8 lanes/row dense lines; TWO row-batches per table read; SOFTWARE
// PIPELINED (next tile's 4 float4 loads overlap current compute).
// ---------------------------------------------------------------------------
__device__ __forceinline__ void k3_compute_store(
    float* __restrict__ out, const float* sc, const float* sd,
    int r0, int r1, int colA, int colB,
    float4 xA0, float4 xB0, float4 xA1, float4 xB1)
{
    float a0[6], a1[6];
#pragma unroll
    for (int t = 0; t < 6; t++) {
        const float4 cA = *reinterpret_cast<const float4*>(sc + (t << 6) + colA);
        const float4 cB = *reinterpret_cast<const float4*>(sc + (t << 6) + colB);
        a0[t] = dot8(xA0, xB0, cA, cB);
        a1[t] = dot8(xA1, xB1, cA, cB);
    }
#pragma unroll
    for (int off = 4; off; off >>= 1)
#pragma unroll
        for (int t = 0; t < 6; t++) {
            a0[t] += __shfl_xor_sync(0xffffffffu, a0[t], off);
            a1[t] += __shfl_xor_sync(0xffffffffu, a1[t], off);
        }

    const float2 h = make_float2(0.05f, 0.05f);
    float2 oA0[2], oB0[2], oA1[2], oB1[2];
    oA0[0] = fmul2(make_float2(xA0.x, xA0.y), h); oA0[1] = fmul2(make_float2(xA0.z, xA0.w), h);
    oB0[0] = fmul2(make_float2(xB0.x, xB0.y), h); oB0[1] = fmul2(make_float2(xB0.z, xB0.w), h);
    oA1[0] = fmul2(make_float2(xA1.x, xA1.y), h); oA1[1] = fmul2(make_float2(xA1.z, xA1.w), h);
    oB1[0] = fmul2(make_float2(xB1.x, xB1.y), h); oB1[1] = fmul2(make_float2(xB1.z, xB1.w), h);
#pragma unroll
    for (int t = 0; t < 6; t++) {
        const float4 dA = *reinterpret_cast<const float4*>(sd + (t << 6) + colA);
        const float4 dB = *reinterpret_cast<const float4*>(sd + (t << 6) + colB);
        const float2 v0 = make_float2(a0[t], a0[t]);
        const float2 v1 = make_float2(a1[t], a1[t]);
        oA0[0] = ffma2(v0, make_float2(dA.x, dA.y), oA0[0]);
        oA0[1] = ffma2(v0, make_float2(dA.z, dA.w), oA0[1]);
        oB0[0] = ffma2(v0, make_float2(dB.x, dB.y), oB0[0]);
        oB0[1] = ffma2(v0, make_float2(dB.z, dB.w), oB0[1]);
        oA1[0] = ffma2(v1, make_float2(dA.x, dA.y), oA1[0]);
        oA1[1] = ffma2(v1, make_float2(dA.z, dA.w), oA1[1]);
        oB1[0] = ffma2(v1, make_float2(dB.x, dB.y), oB1[0]);
        oB1[1] = ffma2(v1, make_float2(dB.z, dB.w), oB1[1]);
    }

    {
        float* po = out + ((size_t)r0 << 6);
        *reinterpret_cast<float4*>(po + colA) =
            make_float4(oA0[0].x, oA0[0].y, oA0[1].x, oA0[1].y);
        *reinterpret_cast<float4*>(po + colB) =
            make_float4(oB0[0].x, oB0[0].y, oB0[1].x, oB0[1].y);
    }
    {
        float* po = out + ((size_t)r1 << 6);
        *reinterpret_cast<float4*>(po + colA) =
            make_float4(oA1[0].x, oA1[0].y, oA1[1].x, oA1[1].y);
        *reinterpret_cast<float4*>(po + colB) =
            make_float4(oB1[0].x, oB1[0].y, oB1[1].x, oB1[1].y);
    }
}

__global__ __launch_bounds__(256, 3) void k3_apply(K3Args A)
{
    const int side = (blockIdx.x >= K3GX) ? 1 : 0;
    const int bid  = side ? (blockIdx.x - K3GX) : blockIdx.x;
    const int nb   = side ? K3GY : K3GX;
    const float* __restrict__ emb = side ? A.embY : A.embX;
    const int*   __restrict__ ids = side ? A.idsY : A.idsX;
    const int n = side ? A.nY : A.nX;
    float* __restrict__ out = side ? A.outY : A.outX;

    __shared__ float sc[384];   // 0.1 * c
    __shared__ float sd[384];
    const int tid = threadIdx.x;
    {
        const float* cv = side ? g_cy : g_cx;
        const float* dv = side ? g_dy : g_dx;
        for (int i = tid; i < 384; i += 256) {
            sc[i] = 0.1f * cv[i];
            sd[i] = dv[i];
        }
    }
    __syncthreads();

    const int wid  = tid >> 5;
    const int lane = tid & 31;
    const int rsl  = (wid << 2) + (lane >> 3);   // 0..31
    const int g    = lane & 7;
    const int colA = g << 2;
    const int colB = 32 + (g << 2);

    const int nfull = n & ~63;   // full-tile limit
    int base = bid * 64;

    if (base + 64 <= nfull) {
        // prologue
        const float* q0 = emb + ((size_t)ids[base + rsl] << 6);
        const float* q1 = emb + ((size_t)ids[base + 32 + rsl] << 6);
        float4 xA0 = *reinterpret_cast<const float4*>(q0 + colA);
        float4 xB0 = *reinterpret_cast<const float4*>(q0 + colB);
        float4 xA1 = *reinterpret_cast<const float4*>(q1 + colA);
        float4 xB1 = *reinterpret_cast<const float4*>(q1 + colB);

        for (;;) {
            const int nbase = base + nb * 64;
            const bool more = nbase + 64 <= nfull;
            float4 nA0, nB0, nA1, nB1;
            if (more) {
                const float* p0 = emb + ((size_t)ids[nbase + rsl] << 6);
                const float* p1 = emb + ((size_t)ids[nbase + 32 + rsl] << 6);
                nA0 = *reinterpret_cast<const float4*>(p0 + colA);
                nB0 = *reinterpret_cast<const float4*>(p0 + colB);
                nA1 = *reinterpret_cast<const float4*>(p1 + colA);
                nB1 = *reinterpret_cast<const float4*>(p1 + colB);
            }

            k3_compute_store(out, sc, sd, base + rsl, base + 32 + rsl,
                             colA, colB, xA0, xB0, xA1, xB1);

            if (!more) { base = nbase; break; }
            base = nbase;
            xA0 = nA0; xB0 = nB0; xA1 = nA1; xB1 = nB1;
        }
    }

    // tail (n % 64 == 32 for both sides): rows [nfull, n)
    if (base < n && nfull < n) {
        // only blocks whose stride lands here do the tail; guard rows >= n
        const int r0 = nfull + rsl;
        if (r0 < n) {
            const float* p = emb + ((size_t)ids[r0] << 6);
            float4 xA0 = *reinterpret_cast<const float4*>(p + colA);
            float4 xB0 = *reinterpret_cast<const float4*>(p + colB);
            // duplicate row into second batch slot (writes same address twice is
            // avoided by using r0 for both and letting the second store win; but
            // cleaner: compute with batch1 = batch0 and store batch0 only).
            float a0[6];
#pragma unroll
            for (int t = 0; t < 6; t++) {
                const float4 cA = *reinterpret_cast<const float4*>(sc + (t << 6) + colA);
                const float4 cB = *reinterpret_cast<const float4*>(sc + (t << 6) + colB);
                a0[t] = dot8(xA0, xB0, cA, cB);
            }
#pragma unroll
            for (int off = 4; off; off >>= 1)
#pragma unroll
                for (int t = 0; t < 6; t++)
                    a0[t] += __shfl_xor_sync(0xffffffffu, a0[t], off);

            const float2 h = make_float2(0.05f, 0.05f);
            float2 oA[2], oB[2];
            oA[0] = fmul2(make_float2(xA0.x, xA0.y), h);
            oA[1] = fmul2(make_float2(xA0.z, xA0.w), h);
            oB[0] = fmul2(make_float2(xB0.x, xB0.y), h);
            oB[1] = fmul2(make_float2(xB0.z, xB0.w), h);
#pragma unroll
            for (int t = 0; t < 6; t++) {
                const float4 dA = *reinterpret_cast<const float4*>(sd + (t << 6) + colA);
                const float4 dB = *reinterpret_cast<const float4*>(sd + (t << 6) + colB);
                const float2 v = make_float2(a0[t], a0[t]);
                oA[0] = ffma2(v, make_float2(dA.x, dA.y), oA[0]);
                oA[1] = ffma2(v, make_float2(dA.z, dA.w), oA[1]);
                oB[0] = ffma2(v, make_float2(dB.x, dB.y), oB[0]);
                oB[1] = ffma2(v, make_float2(dB.z, dB.w), oB[1]);
            }
            float* po = out + ((size_t)r0 << 6);
            *reinterpret_cast<float4*>(po + colA) =
                make_float4(oA[0].x, oA[0].y, oA[1].x, oA[1].y);
            *reinterpret_cast<float4*>(po + colB) =
                make_float4(oB[0].x, oB[0].y, oB[1].x, oB[1].y);
        }
    }
}

// ---------------------------------------------------------------------------
extern "C" void kernel_launch(void* const* d_in, const int* in_sizes, int n_in,
                              void* d_out, int out_size)
{
    const int*   uid = (const int*)d_in[0];
    const int*   iid = (const int*)d_in[1];
    const float* ue  = (const float*)d_in[2];
    const float* ie  = (const float*)d_in[3];
    const int nuser = in_sizes[0];
    const int nitem = in_sizes[1];

    K2Args ka;
    for (int v = 0; v < 12; v++) {
        ka.w[v]  = (const float*)d_in[4 + 2 * v];
        ka.w1[v] = (const float*)d_in[5 + 2 * v];
    }
    ka.edges[0] = (const float*)d_in[28];
    ka.edges[1] = (const float*)d_in[29];
    ka.edges[2] = (const float*)d_in[30];

    K1Args k1a;
    k1a.embX = ue; k1a.idsX = uid; k1a.nX = nuser;
    k1a.embY = ie; k1a.idsY = iid; k1a.nY = nitem;
    for (int b = 0; b < 3; b++) {
        k1a.wX[b]     = ka.w[4 * b + 0]; // uu
        k1a.wX[3 + b] = ka.w[4 * b + 2]; // iu
        k1a.wY[b]     = ka.w[4 * b + 1]; // ui
        k1a.wY[3 + b] = ka.w[4 * b + 3]; // ii
    }

    float* out = (float*)d_out;
    float* edge_out = out + (size_t)(nuser + nitem) * D;

    K3Args k3a;
    k3a.embX = ue; k3a.idsX = uid; k3a.nX = nuser; k3a.outX = out;
    k3a.embY = ie; k3a.idsY = iid; k3a.nY = nitem; k3a.outY = out + (size_t)nuser * D;

    // 4 launches; ncu captures launch #4 = k3_apply.
    k0_zero<<<1, 768>>>();
    k1_gramvec<<<K1GX + K1GY, 256>>>(k1a);
    k2_build<<<13, 64>>>(ka, edge_out);
    k3_apply<<<K3GX + K3GY, 256>>>(k3a);
}

// round 15
// speedup vs baseline: 1.1834x; 1.1834x over previous
#include <cuda_runtime.h>
#include <cstdint>

#define D 64
// k1: 3 blocks/SM -> 444 blocks, X:Y = 3:5
#define K1GX 166
#define K1GY 278
// k3: 4 blocks/SM -> 592 blocks, X:Y = 3:5
#define K3GX 222
#define K3GY 370

// Global accumulators / tables (no allocation allowed)
__device__ float g_P[768];                 // [0:384) Px_stored, [384:768) Py_stored
__device__ float g_cx[384], g_dx[384];
__device__ float g_cy[384], g_dy[384];

struct K1Args {
    const float* embX; const int* idsX; int nX;
    const float* embY; const int* idsY; int nY;
    const float* wX[6];   // uu(buy,cart,pv), iu(buy,cart,pv)
    const float* wY[6];   // ui(buy,cart,pv), ii(buy,cart,pv)
};
struct K2Args {
    const float* w[12];    // logical: buy_uu, buy_ui, buy_iu, buy_ii, cart_*, pv_*
    const float* w1[12];
};
struct K3Args {
    const float* embX; const int* idsX; int nX; float* outX;
    const float* embY; const int* idsY; int nY; float* outY;
};

// packed fp32 FMA (Blackwell f32x2 pipe)
__device__ __forceinline__ float2 ffma2(float2 a, float2 b, float2 c) {
    float2 d;
    asm("{\n\t"
        ".reg .b64 Ar,Br,Cr,Dr;\n\t"
        "mov.b64 Ar,{%2,%3};\n\t"
        "mov.b64 Br,{%4,%5};\n\t"
        "mov.b64 Cr,{%6,%7};\n\t"
        "fma.rn.f32x2 Dr,Ar,Br,Cr;\n\t"
        "mov.b64 {%0,%1},Dr;\n\t"
        "}" : "=f"(d.x), "=f"(d.y)
            : "f"(a.x), "f"(a.y), "f"(b.x), "f"(b.y), "f"(c.x), "f"(c.y));
    return d;
}
__device__ __forceinline__ float2 fmul2(float2 a, float2 b) {
    return ffma2(a, b, make_float2(0.f, 0.f));
}
__device__ __forceinline__ float dot8(float4 a0, float4 a1, float4 b0, float4 b1) {
    float2 s = fmul2(make_float2(a0.x, a0.y), make_float2(b0.x, b0.y));
    s = ffma2(make_float2(a0.z, a0.w), make_float2(b0.z, b0.w), s);
    s = ffma2(make_float2(a1.x, a1.y), make_float2(b1.x, b1.y), s);
    s = ffma2(make_float2(a1.z, a1.w), make_float2(b1.z, b1.w), s);
    return s.x + s.y;
}

// ---------------------------------------------------------------------------
__global__ void k0a_zero() { g_P[threadIdx.x] = 0.0f; }          // [0:384)
__global__ void k0b_zero() { g_P[384 + threadIdx.x] = 0.0f; }    // [384:768)

__global__ void k_edge(const float* __restrict__ e0, const float* __restrict__ e1,
                       const float* __restrict__ e2, float* __restrict__ out)
{
    const int j = threadIdx.x;
    out[j] = e0[j]; out[64 + j] = e1[j]; out[128 + j] = e2[j];
}

// ---------------------------------------------------------------------------
// k1: p_t(stored) = sum_rows (x . 0.1*w_t) x_raw.
// 8 lanes/row dense lines; warp pair shares 4 rows, t-split; w in shared.
// TWO-STAGE pipeline: ids prefetched 2 iters ahead, x 1 iter ahead, so the
// ids->addr->x chains overlap compute instead of serializing.
// ---------------------------------------------------------------------------
__global__ __launch_bounds__(256, 3) void k1_gramvec(K1Args A)
{
    const int side = (blockIdx.x >= K1GX) ? 1 : 0;
    const int bid  = side ? (blockIdx.x - K1GX) : blockIdx.x;
    const int nb   = side ? K1GY : K1GX;
    const float* __restrict__ emb = side ? A.embY : A.embX;
    const int*   __restrict__ ids = side ? A.idsY : A.idsX;
    const int n = side ? A.nY : A.nX;

    __shared__ float sw[384];     // 0.1 * w
    __shared__ float sp[384];
    const int tid  = threadIdx.x;
    const int wid  = tid >> 5;
    const int lane = tid & 31;
    const int tg   = (wid & 1) * 3;
    const int rsl  = ((wid >> 1) << 2) + (lane >> 3);
    const int g    = lane & 7;
    const int colA = g << 2;
    const int colB = 32 + (g << 2);

    {
        const float* const* Wp = side ? A.wY : A.wX;
        for (int i = tid; i < 384; i += 256) {
            sw[i] = 0.1f * Wp[i >> 6][i & 63];
            sp[i] = 0.0f;
        }
    }
    __syncthreads();

    float2 accA[3][2], accB[3][2];
#pragma unroll
    for (int t = 0; t < 3; t++) {
        accA[t][0] = accA[t][1] = make_float2(0.f, 0.f);
        accB[t][0] = accB[t][1] = make_float2(0.f, 0.f);
    }

    const int stride = nb * 16;
    int base = bid * 16;

    // prologue: id[0] -> x[0]; id[1]
    {
        const float* p0 = emb + ((size_t)ids[base + rsl] << 6);
        // fallthrough loads below
        float4 xA = *reinterpret_cast<const float4*>(p0 + colA);
        float4 xB = *reinterpret_cast<const float4*>(p0 + colB);
        int id1 = (base + stride < n) ? ids[base + stride + rsl] : 0;

        for (;;) {
            const int nbase = base + stride;
            const bool more  = nbase < n;
            const bool more2 = nbase + stride < n;

            // prefetch ids two iterations ahead (starts chain early)
            const int id2 = more2 ? ids[nbase + stride + rsl] : 0;

            // prefetch x one iteration ahead (id1 already resident)
            float4 xAn, xBn;
            if (more) {
                const float* pn = emb + ((size_t)id1 << 6);
                xAn = *reinterpret_cast<const float4*>(pn + colA);
                xBn = *reinterpret_cast<const float4*>(pn + colB);
            }

            // compute on current x
            float a[3];
#pragma unroll
            for (int t = 0; t < 3; t++) {
                const float4 wA = *reinterpret_cast<const float4*>(sw + ((tg + t) << 6) + colA);
                const float4 wB = *reinterpret_cast<const float4*>(sw + ((tg + t) << 6) + colB);
                a[t] = dot8(xA, xB, wA, wB);
            }
#pragma unroll
            for (int off = 4; off; off >>= 1)
#pragma unroll
                for (int t = 0; t < 3; t++)
                    a[t] += __shfl_xor_sync(0xffffffffu, a[t], off);
#pragma unroll
            for (int t = 0; t < 3; t++) {
                const float2 av = make_float2(a[t], a[t]);
                accA[t][0] = ffma2(av, make_float2(xA.x, xA.y), accA[t][0]);
                accA[t][1] = ffma2(av, make_float2(xA.z, xA.w), accA[t][1]);
                accB[t][0] = ffma2(av, make_float2(xB.x, xB.y), accB[t][0]);
                accB[t][1] = ffma2(av, make_float2(xB.z, xB.w), accB[t][1]);
            }

            if (!more) break;
            base = nbase;
            id1 = id2;
            xA = xAn; xB = xBn;
        }
    }

    // fold the 4 row-groups per warp (off 8, 16)
#pragma unroll
    for (int off = 8; off <= 16; off <<= 1)
#pragma unroll
        for (int t = 0; t < 3; t++)
#pragma unroll
            for (int j = 0; j < 2; j++) {
                accA[t][j].x += __shfl_xor_sync(0xffffffffu, accA[t][j].x, off);
                accA[t][j].y += __shfl_xor_sync(0xffffffffu, accA[t][j].y, off);
                accB[t][j].x += __shfl_xor_sync(0xffffffffu, accB[t][j].x, off);
                accB[t][j].y += __shfl_xor_sync(0xffffffffu, accB[t][j].y, off);
            }

    if (lane < 8) {
#pragma unroll
        for (int t = 0; t < 3; t++) {
            atomicAdd(&sp[((tg + t) << 6) + colA],     accA[t][0].x);
            atomicAdd(&sp[((tg + t) << 6) + colA + 1], accA[t][0].y);
            atomicAdd(&sp[((tg + t) << 6) + colA + 2], accA[t][1].x);
            atomicAdd(&sp[((tg + t) << 6) + colA + 3], accA[t][1].y);
            atomicAdd(&sp[((tg + t) << 6) + colB],     accB[t][0].x);
            atomicAdd(&sp[((tg + t) << 6) + colB + 1], accB[t][0].y);
            atomicAdd(&sp[((tg + t) << 6) + colB + 2], accB[t][1].x);
            atomicAdd(&sp[((tg + t) << 6) + colB + 3], accB[t][1].y);
        }
    }
    __syncthreads();

    float* gp = g_P + side * 384;
    for (int i = tid; i < 384; i += 256)
        atomicAdd(&gp[i], sp[i]);
}

// ---------------------------------------------------------------------------
// k2: build c/d tables. Blocks 0..11: one (side,term).
// p_true = 0.1 * p_stored -> coef = 0.25 * 0.1 * W_b
// ---------------------------------------------------------------------------
__global__ __launch_bounds__(64) void k2_build(K2Args a)
{
    const int blk = blockIdx.x;
    const int j   = threadIdx.x;
    const int side = blk / 6;
    const int t    = blk % 6;
    const int b    = t % 3;

    const float* p; const float* W1; const float* c;
    if (side == 0) {
        if (t < 3) { p = &g_P[b * 64];           W1 = a.w1[4 * b + 0]; c = a.w[4 * b + 0]; } // uu
        else       { p = &g_P[384 + b * 64];     W1 = a.w1[4 * b + 1]; c = a.w[4 * b + 1]; } // ui
    } else {
        if (t < 3) { p = &g_P[384 + (3 + b) * 64]; W1 = a.w1[4 * b + 3]; c = a.w[4 * b + 3]; } // ii
        else       { p = &g_P[(3 + b) * 64];       W1 = a.w1[4 * b + 2]; c = a.w[4 * b + 2]; } // iu
    }
    const float coef = 0.025f * ((b == 0) ? 0.6f : (b == 1) ? 0.3f : 0.1f);

    float u0 = 0.f, u1 = 0.f, u2 = 0.f, u3 = 0.f;
#pragma unroll
    for (int k = 0; k < 64; k += 4) {
        u0 += p[k + 0] * W1[(k + 0) * 64 + j];
        u1 += p[k + 1] * W1[(k + 1) * 64 + j];
        u2 += p[k + 2] * W1[(k + 2) * 64 + j];
        u3 += p[k + 3] * W1[(k + 3) * 64 + j];
    }
    const float d = coef * ((u0 + u1) + (u2 + u3));
    if (side == 0) { g_dx[t * 64 + j] = d; g_cx[t * 64 + j] = c[j]; }
    else           { g_dy[t * 64 + j] = d; g_cy[t * 64 + j] = c[j]; }
}

// ---------------------------------------------------------------------------
// k3: out = 0.05*x_raw + sum_t (x_raw . 0.1c_t) d_t     (R10 exact: best)
// 8 lanes/row dense lines; TWO row-batches share each table read.
// 64 rows per block-iter; tail handled by guarded pass.
// ---------------------------------------------------------------------------
template <bool GUARD>
__device__ __forceinline__ void k3_batch(
    const float* __restrict__ emb, const int* __restrict__ ids, int n,
    float* __restrict__ out, const float* sc, const float* sd,
    int r0, int r1, int colA, int colB)
{
    const bool ok0 = !GUARD || (r0 < n);
    const bool ok1 = !GUARD || (r1 < n);
    float4 xA0, xB0, xA1, xB1;
    if (ok0) {
        const float* p = emb + ((size_t)ids[r0] << 6);
        xA0 = *reinterpret_cast<const float4*>(p + colA);
        xB0 = *reinterpret_cast<const float4*>(p + colB);
    } else { xA0 = xB0 = make_float4(0.f, 0.f, 0.f, 0.f); }
    if (ok1) {
        const float* p = emb + ((size_t)ids[r1] << 6);
        xA1 = *reinterpret_cast<const float4*>(p + colA);
        xB1 = *reinterpret_cast<const float4*>(p + colB);
    } else { xA1 = xB1 = make_float4(0.f, 0.f, 0.f, 0.f); }

    float a0[6], a1[6];
#pragma unroll
    for (int t = 0; t < 6; t++) {
        const float4 cA = *reinterpret_cast<const float4*>(sc + (t << 6) + colA);
        const float4 cB = *reinterpret_cast<const float4*>(sc + (t << 6) + colB);
        a0[t] = dot8(xA0, xB0, cA, cB);
        a1[t] = dot8(xA1, xB1, cA, cB);
    }
#pragma unroll
    for (int off = 4; off; off >>= 1)
#pragma unroll
        for (int t = 0; t < 6; t++) {
            a0[t] += __shfl_xor_sync(0xffffffffu, a0[t], off);
            a1[t] += __shfl_xor_sync(0xffffffffu, a1[t], off);
        }

    const float2 h = make_float2(0.05f, 0.05f);
    float2 oA0[2], oB0[2], oA1[2], oB1[2];
    oA0[0] = fmul2(make_float2(xA0.x, xA0.y), h); oA0[1] = fmul2(make_float2(xA0.z, xA0.w), h);
    oB0[0] = fmul2(make_float2(xB0.x, xB0.y), h); oB0[1] = fmul2(make_float2(xB0.z, xB0.w), h);
    oA1[0] = fmul2(make_float2(xA1.x, xA1.y), h); oA1[1] = fmul2(make_float2(xA1.z, xA1.w), h);
    oB1[0] = fmul2(make_float2(xB1.x, xB1.y), h); oB1[1] = fmul2(make_float2(xB1.z, xB1.w), h);
#pragma unroll
    for (int t = 0; t < 6; t++) {
        const float4 dA = *reinterpret_cast<const float4*>(sd + (t << 6) + colA);
        const float4 dB = *reinterpret_cast<const float4*>(sd + (t << 6) + colB);
        const float2 v0 = make_float2(a0[t], a0[t]);
        const float2 v1 = make_float2(a1[t], a1[t]);
        oA0[0] = ffma2(v0, make_float2(dA.x, dA.y), oA0[0]);
        oA0[1] = ffma2(v0, make_float2(dA.z, dA.w), oA0[1]);
        oB0[0] = ffma2(v0, make_float2(dB.x, dB.y), oB0[0]);
        oB0[1] = ffma2(v0, make_float2(dB.z, dB.w), oB0[1]);
        oA1[0] = ffma2(v1, make_float2(dA.x, dA.y), oA1[0]);
        oA1[1] = ffma2(v1, make_float2(dA.z, dA.w), oA1[1]);
        oB1[0] = ffma2(v1, make_float2(dB.x, dB.y), oB1[0]);
        oB1[1] = ffma2(v1, make_float2(dB.z, dB.w), oB1[1]);
    }

    if (ok0) {
        float* po = out + ((size_t)r0 << 6);
        *reinterpret_cast<float4*>(po + colA) =
            make_float4(oA0[0].x, oA0[0].y, oA0[1].x, oA0[1].y);
        *reinterpret_cast<float4*>(po + colB) =
            make_float4(oB0[0].x, oB0[0].y, oB0[1].x, oB0[1].y);
    }
    if (ok1) {
        float* po = out + ((size_t)r1 << 6);
        *reinterpret_cast<float4*>(po + colA) =
            make_float4(oA1[0].x, oA1[0].y, oA1[1].x, oA1[1].y);
        *reinterpret_cast<float4*>(po + colB) =
            make_float4(oB1[0].x, oB1[0].y, oB1[1].x, oB1[1].y);
    }
}

__global__ __launch_bounds__(256, 4) void k3_apply(K3Args A)
{
    const int side = (blockIdx.x >= K3GX) ? 1 : 0;
    const int bid  = side ? (blockIdx.x - K3GX) : blockIdx.x;
    const int nb   = side ? K3GY : K3GX;
    const float* __restrict__ emb = side ? A.embY : A.embX;
    const int*   __restrict__ ids = side ? A.idsY : A.idsX;
    const int n = side ? A.nY : A.nX;
    float* __restrict__ out = side ? A.outY : A.outX;

    __shared__ float sc[384];   // 0.1 * c
    __shared__ float sd[384];
    const int tid = threadIdx.x;
    {
        const float* cv = side ? g_cy : g_cx;
        const float* dv = side ? g_dy : g_dx;
        for (int i = tid; i < 384; i += 256) {
            sc[i] = 0.1f * cv[i];
            sd[i] = dv[i];
        }
    }
    __syncthreads();

    const int wid  = tid >> 5;
    const int lane = tid & 31;
    const int rsl  = (wid << 2) + (lane >> 3);   // 0..31
    const int g    = lane & 7;
    const int colA = g << 2;
    const int colB = 32 + (g << 2);

    int base = bid * 64;
    for (; base + 64 <= n; base += nb * 64)
        k3_batch<false>(emb, ids, n, out, sc, sd,
                        base + rsl, base + 32 + rsl, colA, colB);
    if (base < n)
        k3_batch<true>(emb, ids, n, out, sc, sd,
                       base + rsl, base + 32 + rsl, colA, colB);
}

// ---------------------------------------------------------------------------
extern "C" void kernel_launch(void* const* d_in, const int* in_sizes, int n_in,
                              void* d_out, int out_size)
{
    const int*   uid = (const int*)d_in[0];
    const int*   iid = (const int*)d_in[1];
    const float* ue  = (const float*)d_in[2];
    const float* ie  = (const float*)d_in[3];
    const int nuser = in_sizes[0];
    const int nitem = in_sizes[1];

    K2Args ka;
    for (int v = 0; v < 12; v++) {
        ka.w[v]  = (const float*)d_in[4 + 2 * v];
        ka.w1[v] = (const float*)d_in[5 + 2 * v];
    }

    K1Args k1a;
    k1a.embX = ue; k1a.idsX = uid; k1a.nX = nuser;
    k1a.embY = ie; k1a.idsY = iid; k1a.nY = nitem;
    for (int b = 0; b < 3; b++) {
        k1a.wX[b]     = ka.w[4 * b + 0]; // uu
        k1a.wX[3 + b] = ka.w[4 * b + 2]; // iu
        k1a.wY[b]     = ka.w[4 * b + 1]; // ui
        k1a.wY[3 + b] = ka.w[4 * b + 3]; // ii
    }

    float* out = (float*)d_out;
    float* edge_out = out + (size_t)(nuser + nitem) * D;

    K3Args k3a;
    k3a.embX = ue; k3a.idsX = uid; k3a.nX = nuser; k3a.outX = out;
    k3a.embY = ie; k3a.idsY = iid; k3a.nY = nitem; k3a.outY = out + (size_t)nuser * D;

    // 6 launches; ncu captures launch #4 = k1_gramvec.
    k0a_zero<<<1, 384>>>();
    k0b_zero<<<1, 384>>>();
    k_edge<<<1, 64>>>((const float*)d_in[28], (const float*)d_in[29],
                      (const float*)d_in[30], edge_out);
    k1_gramvec<<<K1GX + K1GY, 256>>>(k1a);
    k2_build<<<12, 64>>>(ka);
    k3_apply<<<K3GX + K3GY, 256>>>(k3a);
}

// round 16
// speedup vs baseline: 1.2080x; 1.0208x over previous
#include <cuda_runtime.h>
#include <cstdint>

#define D 64
// k1: 3 blocks/SM @256thr -> 444 blocks, X:Y = 3:5
#define K1GX 166
#define K1GY 278
// k3: 8 blocks/SM @128thr -> 1184 blocks, X:Y = 3:5
#define K3GX 444
#define K3GY 740

// Global accumulators / tables (no allocation allowed)
__device__ float g_P[768];                 // [0:384) Px_stored, [384:768) Py_stored
__device__ float g_cx[384], g_dx[384];
__device__ float g_cy[384], g_dy[384];

struct K1Args {
    const float* embX; const int* idsX; int nX;
    const float* embY; const int* idsY; int nY;
    const float* wX[6];   // uu(buy,cart,pv), iu(buy,cart,pv)
    const float* wY[6];   // ui(buy,cart,pv), ii(buy,cart,pv)
};
struct K2Args {
    const float* w[12];    // logical: buy_uu, buy_ui, buy_iu, buy_ii, cart_*, pv_*
    const float* w1[12];
    const float* edges[3];
};
struct K3Args {
    const float* embX; const int* idsX; int nX; float* outX;
    const float* embY; const int* idsY; int nY; float* outY;
};

// packed fp32 FMA (Blackwell f32x2 pipe)
__device__ __forceinline__ float2 ffma2(float2 a, float2 b, float2 c) {
    float2 d;
    asm("{\n\t"
        ".reg .b64 Ar,Br,Cr,Dr;\n\t"
        "mov.b64 Ar,{%2,%3};\n\t"
        "mov.b64 Br,{%4,%5};\n\t"
        "mov.b64 Cr,{%6,%7};\n\t"
        "fma.rn.f32x2 Dr,Ar,Br,Cr;\n\t"
        "mov.b64 {%0,%1},Dr;\n\t"
        "}" : "=f"(d.x), "=f"(d.y)
            : "f"(a.x), "f"(a.y), "f"(b.x), "f"(b.y), "f"(c.x), "f"(c.y));
    return d;
}
__device__ __forceinline__ float2 fmul2(float2 a, float2 b) {
    return ffma2(a, b, make_float2(0.f, 0.f));
}
__device__ __forceinline__ float dot8(float4 a0, float4 a1, float4 b0, float4 b1) {
    float2 s = fmul2(make_float2(a0.x, a0.y), make_float2(b0.x, b0.y));
    s = ffma2(make_float2(a0.z, a0.w), make_float2(b0.z, b0.w), s);
    s = ffma2(make_float2(a1.x, a1.y), make_float2(b1.x, b1.y), s);
    s = ffma2(make_float2(a1.z, a1.w), make_float2(b1.z, b1.w), s);
    return s.x + s.y;
}

// ---------------------------------------------------------------------------
__global__ void k0_zero() { g_P[threadIdx.x] = 0.0f; }

// ---------------------------------------------------------------------------
// k1: p_t(stored) = sum_rows (x . 0.1*w_t) x_raw.  (R15 version: proven)
// 8 lanes/row dense lines; warp pair shares 4 rows, t-split; w in shared.
// TWO-STAGE pipeline: ids 2 iters ahead, x 1 iter ahead.
// ---------------------------------------------------------------------------
__global__ __launch_bounds__(256, 3) void k1_gramvec(K1Args A)
{
    const int side = (blockIdx.x >= K1GX) ? 1 : 0;
    const int bid  = side ? (blockIdx.x - K1GX) : blockIdx.x;
    const int nb   = side ? K1GY : K1GX;
    const float* __restrict__ emb = side ? A.embY : A.embX;
    const int*   __restrict__ ids = side ? A.idsY : A.idsX;
    const int n = side ? A.nY : A.nX;

    __shared__ float sw[384];     // 0.1 * w
    __shared__ float sp[384];
    const int tid  = threadIdx.x;
    const int wid  = tid >> 5;
    const int lane = tid & 31;
    const int tg   = (wid & 1) * 3;
    const int rsl  = ((wid >> 1) << 2) + (lane >> 3);
    const int g    = lane & 7;
    const int colA = g << 2;
    const int colB = 32 + (g << 2);

    {
        const float* const* Wp = side ? A.wY : A.wX;
        for (int i = tid; i < 384; i += 256) {
            sw[i] = 0.1f * Wp[i >> 6][i & 63];
            sp[i] = 0.0f;
        }
    }
    __syncthreads();

    float2 accA[3][2], accB[3][2];
#pragma unroll
    for (int t = 0; t < 3; t++) {
        accA[t][0] = accA[t][1] = make_float2(0.f, 0.f);
        accB[t][0] = accB[t][1] = make_float2(0.f, 0.f);
    }

    const int stride = nb * 16;
    int base = bid * 16;

    {
        const float* p0 = emb + ((size_t)ids[base + rsl] << 6);
        float4 xA = *reinterpret_cast<const float4*>(p0 + colA);
        float4 xB = *reinterpret_cast<const float4*>(p0 + colB);
        int id1 = (base + stride < n) ? ids[base + stride + rsl] : 0;

        for (;;) {
            const int nbase = base + stride;
            const bool more  = nbase < n;
            const bool more2 = nbase + stride < n;

            const int id2 = more2 ? ids[nbase + stride + rsl] : 0;

            float4 xAn, xBn;
            if (more) {
                const float* pn = emb + ((size_t)id1 << 6);
                xAn = *reinterpret_cast<const float4*>(pn + colA);
                xBn = *reinterpret_cast<const float4*>(pn + colB);
            }

            float a[3];
#pragma unroll
            for (int t = 0; t < 3; t++) {
                const float4 wA = *reinterpret_cast<const float4*>(sw + ((tg + t) << 6) + colA);
                const float4 wB = *reinterpret_cast<const float4*>(sw + ((tg + t) << 6) + colB);
                a[t] = dot8(xA, xB, wA, wB);
            }
#pragma unroll
            for (int off = 4; off; off >>= 1)
#pragma unroll
                for (int t = 0; t < 3; t++)
                    a[t] += __shfl_xor_sync(0xffffffffu, a[t], off);
#pragma unroll
            for (int t = 0; t < 3; t++) {
                const float2 av = make_float2(a[t], a[t]);
                accA[t][0] = ffma2(av, make_float2(xA.x, xA.y), accA[t][0]);
                accA[t][1] = ffma2(av, make_float2(xA.z, xA.w), accA[t][1]);
                accB[t][0] = ffma2(av, make_float2(xB.x, xB.y), accB[t][0]);
                accB[t][1] = ffma2(av, make_float2(xB.z, xB.w), accB[t][1]);
            }

            if (!more) break;
            base = nbase;
            id1 = id2;
            xA = xAn; xB = xBn;
        }
    }

#pragma unroll
    for (int off = 8; off <= 16; off <<= 1)
#pragma unroll
        for (int t = 0; t < 3; t++)
#pragma unroll
            for (int j = 0; j < 2; j++) {
                accA[t][j].x += __shfl_xor_sync(0xffffffffu, accA[t][j].x, off);
                accA[t][j].y += __shfl_xor_sync(0xffffffffu, accA[t][j].y, off);
                accB[t][j].x += __shfl_xor_sync(0xffffffffu, accB[t][j].x, off);
                accB[t][j].y += __shfl_xor_sync(0xffffffffu, accB[t][j].y, off);
            }

    if (lane < 8) {
#pragma unroll
        for (int t = 0; t < 3; t++) {
            atomicAdd(&sp[((tg + t) << 6) + colA],     accA[t][0].x);
            atomicAdd(&sp[((tg + t) << 6) + colA + 1], accA[t][0].y);
            atomicAdd(&sp[((tg + t) << 6) + colA + 2], accA[t][1].x);
            atomicAdd(&sp[((tg + t) << 6) + colA + 3], accA[t][1].y);
            atomicAdd(&sp[((tg + t) << 6) + colB],     accB[t][0].x);
            atomicAdd(&sp[((tg + t) << 6) + colB + 1], accB[t][0].y);
            atomicAdd(&sp[((tg + t) << 6) + colB + 2], accB[t][1].x);
            atomicAdd(&sp[((tg + t) << 6) + colB + 3], accB[t][1].y);
        }
    }
    __syncthreads();

    float* gp = g_P + side * 384;
    for (int i = tid; i < 384; i += 256)
        atomicAdd(&gp[i], sp[i]);
}

// ---------------------------------------------------------------------------
// k2: build c/d tables. Blocks 0..11: one (side,term). Block 12: edge copy.
// p_true = 0.1 * p_stored -> coef = 0.25 * 0.1 * W_b
// ---------------------------------------------------------------------------
__global__ __launch_bounds__(64) void k2_build(K2Args a, float* __restrict__ edge_out)
{
    const int blk = blockIdx.x;
    const int j   = threadIdx.x;

    if (blk == 12) {
#pragma unroll
        for (int e = 0; e < 3; e++)
            edge_out[e * 64 + j] = a.edges[e][j];
        return;
    }

    const int side = blk / 6;
    const int t    = blk % 6;
    const int b    = t % 3;

    const float* p; const float* W1; const float* c;
    if (side == 0) {
        if (t < 3) { p = &g_P[b * 64];           W1 = a.w1[4 * b + 0]; c = a.w[4 * b + 0]; } // uu
        else       { p = &g_P[384 + b * 64];     W1 = a.w1[4 * b + 1]; c = a.w[4 * b + 1]; } // ui
    } else {
        if (t < 3) { p = &g_P[384 + (3 + b) * 64]; W1 = a.w1[4 * b + 3]; c = a.w[4 * b + 3]; } // ii
        else       { p = &g_P[(3 + b) * 64];       W1 = a.w1[4 * b + 2]; c = a.w[4 * b + 2]; } // iu
    }
    const float coef = 0.025f * ((b == 0) ? 0.6f : (b == 1) ? 0.3f : 0.1f);

    float u0 = 0.f, u1 = 0.f, u2 = 0.f, u3 = 0.f;
#pragma unroll
    for (int k = 0; k < 64; k += 4) {
        u0 += p[k + 0] * W1[(k + 0) * 64 + j];
        u1 += p[k + 1] * W1[(k + 1) * 64 + j];
        u2 += p[k + 2] * W1[(k + 2) * 64 + j];
        u3 += p[k + 3] * W1[(k + 3) * 64 + j];
    }
    const float d = coef * ((u0 + u1) + (u2 + u3));
    if (side == 0) { g_dx[t * 64 + j] = d; g_cx[t * 64 + j] = c[j]; }
    else           { g_dy[t * 64 + j] = d; g_cy[t * 64 + j] = c[j]; }
}

// ---------------------------------------------------------------------------
// k3: out = 0.05*x_raw + sum_t (x_raw . 0.1c_t) d_t
// R10 structure (two row-batches per table read, dense lines) but with
// 128-thread blocks @ 8 blocks/SM for finer residency granularity.
// 32 rows per block-iter; tail handled by guarded pass.
// ---------------------------------------------------------------------------
template <bool GUARD>
__device__ __forceinline__ void k3_batch(
    const float* __restrict__ emb, const int* __restrict__ ids, int n,
    float* __restrict__ out, const float* sc, const float* sd,
    int r0, int r1, int colA, int colB)
{
    const bool ok0 = !GUARD || (r0 < n);
    const bool ok1 = !GUARD || (r1 < n);
    float4 xA0, xB0, xA1, xB1;
    if (ok0) {
        const float* p = emb + ((size_t)ids[r0] << 6);
        xA0 = *reinterpret_cast<const float4*>(p + colA);
        xB0 = *reinterpret_cast<const float4*>(p + colB);
    } else { xA0 = xB0 = make_float4(0.f, 0.f, 0.f, 0.f); }
    if (ok1) {
        const float* p = emb + ((size_t)ids[r1] << 6);
        xA1 = *reinterpret_cast<const float4*>(p + colA);
        xB1 = *reinterpret_cast<const float4*>(p + colB);
    } else { xA1 = xB1 = make_float4(0.f, 0.f, 0.f, 0.f); }

    float a0[6], a1[6];
#pragma unroll
    for (int t = 0; t < 6; t++) {
        const float4 cA = *reinterpret_cast<const float4*>(sc + (t << 6) + colA);
        const float4 cB = *reinterpret_cast<const float4*>(sc + (t << 6) + colB);
        a0[t] = dot8(xA0, xB0, cA, cB);
        a1[t] = dot8(xA1, xB1, cA, cB);
    }
#pragma unroll
    for (int off = 4; off; off >>= 1)
#pragma unroll
        for (int t = 0; t < 6; t++) {
            a0[t] += __shfl_xor_sync(0xffffffffu, a0[t], off);
            a1[t] += __shfl_xor_sync(0xffffffffu, a1[t], off);
        }

    const float2 h = make_float2(0.05f, 0.05f);
    float2 oA0[2], oB0[2], oA1[2], oB1[2];
    oA0[0] = fmul2(make_float2(xA0.x, xA0.y), h); oA0[1] = fmul2(make_float2(xA0.z, xA0.w), h);
    oB0[0] = fmul2(make_float2(xB0.x, xB0.y), h); oB0[1] = fmul2(make_float2(xB0.z, xB0.w), h);
    oA1[0] = fmul2(make_float2(xA1.x, xA1.y), h); oA1[1] = fmul2(make_float2(xA1.z, xA1.w), h);
    oB1[0] = fmul2(make_float2(xB1.x, xB1.y), h); oB1[1] = fmul2(make_float2(xB1.z, xB1.w), h);
#pragma unroll
    for (int t = 0; t < 6; t++) {
        const float4 dA = *reinterpret_cast<const float4*>(sd + (t << 6) + colA);
        const float4 dB = *reinterpret_cast<const float4*>(sd + (t << 6) + colB);
        const float2 v0 = make_float2(a0[t], a0[t]);
        const float2 v1 = make_float2(a1[t], a1[t]);
        oA0[0] = ffma2(v0, make_float2(dA.x, dA.y), oA0[0]);
        oA0[1] = ffma2(v0, make_float2(dA.z, dA.w), oA0[1]);
        oB0[0] = ffma2(v0, make_float2(dB.x, dB.y), oB0[0]);
        oB0[1] = ffma2(v0, make_float2(dB.z, dB.w), oB0[1]);
        oA1[0] = ffma2(v1, make_float2(dA.x, dA.y), oA1[0]);
        oA1[1] = ffma2(v1, make_float2(dA.z, dA.w), oA1[1]);
        oB1[0] = ffma2(v1, make_float2(dB.x, dB.y), oB1[0]);
        oB1[1] = ffma2(v1, make_float2(dB.z, dB.w), oB1[1]);
    }

    if (ok0) {
        float* po = out + ((size_t)r0 << 6);
        *reinterpret_cast<float4*>(po + colA) =
            make_float4(oA0[0].x, oA0[0].y, oA0[1].x, oA0[1].y);
        *reinterpret_cast<float4*>(po + colB) =
            make_float4(oB0[0].x, oB0[0].y, oB0[1].x, oB0[1].y);
    }
    if (ok1) {
        float* po = out + ((size_t)r1 << 6);
        *reinterpret_cast<float4*>(po + colA) =
            make_float4(oA1[0].x, oA1[0].y, oA1[1].x, oA1[1].y);
        *reinterpret_cast<float4*>(po + colB) =
            make_float4(oB1[0].x, oB1[0].y, oB1[1].x, oB1[1].y);
    }
}

__global__ __launch_bounds__(128, 8) void k3_apply(K3Args A)
{
    const int side = (blockIdx.x >= K3GX) ? 1 : 0;
    const int bid  = side ? (blockIdx.x - K3GX) : blockIdx.x;
    const int nb   = side ? K3GY : K3GX;
    const float* __restrict__ emb = side ? A.embY : A.embX;
    const int*   __restrict__ ids = side ? A.idsY : A.idsX;
    const int n = side ? A.nY : A.nX;
    float* __restrict__ out = side ? A.outY : A.outX;

    __shared__ float sc[384];   // 0.1 * c
    __shared__ float sd[384];
    const int tid = threadIdx.x;
    {
        const float* cv = side ? g_cy : g_cx;
        const float* dv = side ? g_dy : g_dx;
        for (int i = tid; i < 384; i += 128) {
            sc[i] = 0.1f * cv[i];
            sd[i] = dv[i];
        }
    }
    __syncthreads();

    const int wid  = tid >> 5;        // 0..3
    const int lane = tid & 31;
    const int rsl  = (wid << 2) + (lane >> 3);   // 0..15
    const int g    = lane & 7;
    const int colA = g << 2;
    const int colB = 32 + (g << 2);

    int base = bid * 32;
    for (; base + 32 <= n; base += nb * 32)
        k3_batch<false>(emb, ids, n, out, sc, sd,
                        base + rsl, base + 16 + rsl, colA, colB);
    if (base < n)
        k3_batch<true>(emb, ids, n, out, sc, sd,
                       base + rsl, base + 16 + rsl, colA, colB);
}

// ---------------------------------------------------------------------------
extern "C" void kernel_launch(void* const* d_in, const int* in_sizes, int n_in,
                              void* d_out, int out_size)
{
    const int*   uid = (const int*)d_in[0];
    const int*   iid = (const int*)d_in[1];
    const float* ue  = (const float*)d_in[2];
    const float* ie  = (const float*)d_in[3];
    const int nuser = in_sizes[0];
    const int nitem = in_sizes[1];

    K2Args ka;
    for (int v = 0; v < 12; v++) {
        ka.w[v]  = (const float*)d_in[4 + 2 * v];
        ka.w1[v] = (const float*)d_in[5 + 2 * v];
    }
    ka.edges[0] = (const float*)d_in[28];
    ka.edges[1] = (const float*)d_in[29];
    ka.edges[2] = (const float*)d_in[30];

    K1Args k1a;
    k1a.embX = ue; k1a.idsX = uid; k1a.nX = nuser;
    k1a.embY = ie; k1a.idsY = iid; k1a.nY = nitem;
    for (int b = 0; b < 3; b++) {
        k1a.wX[b]     = ka.w[4 * b + 0]; // uu
        k1a.wX[3 + b] = ka.w[4 * b + 2]; // iu
        k1a.wY[b]     = ka.w[4 * b + 1]; // ui
        k1a.wY[3 + b] = ka.w[4 * b + 3]; // ii
    }

    float* out = (float*)d_out;
    float* edge_out = out + (size_t)(nuser + nitem) * D;

    K3Args k3a;
    k3a.embX = ue; k3a.idsX = uid; k3a.nX = nuser; k3a.outX = out;
    k3a.embY = ie; k3a.idsY = iid; k3a.nY = nitem; k3a.outY = out + (size_t)nuser * D;

    // 4 launches; ncu captures launch #4 = k3_apply (new 128-thread variant).
    k0_zero<<<1, 768>>>();
    k1_gramvec<<<K1GX + K1GY, 256>>>(k1a);
    k2_build<<<13, 64>>>(ka, edge_out);
    k3_apply<<<K3GX + K3GY, 128>>>(k3a);
}